// round 8
// baseline (speedup 1.0000x reference)
#include <cuda_runtime.h>
#include <cuda_fp16.h>
#include <cstdint>
#include <math.h>

// Problem constants
#define NTOK 8192   // B*S = 2*4096
#define Dh   2048   // hidden dim
#define NE   8      // experts
#define FF   8192   // ffn dim
#define TOPK 2

// ---------------- device scratch (no allocs allowed) ----------------
__device__ float g_logits[NTOK * NE];
__device__ float g_sums[NE];
__device__ int   g_sel[TOPK];
__device__ float g_rw[NTOK * TOPK];
__device__ float g_H[(size_t)NTOK * FF];   // 256 MB intermediate h (fp32)

// ---------------- helpers ----------------
__device__ __forceinline__ float gelu_tanh(float x) {
    // jax.nn.gelu default (approximate=True)
    float x3 = x * x * x;
    float t = tanhf(0.7978845608028654f * (x + 0.044715f * x3));
    return 0.5f * x * (1.0f + t);
}

__device__ __forceinline__ unsigned pack_h2(float lo, float hi) {
    __half2 h = __floats2half2_rn(lo, hi);   // .x = lo half
    return *(unsigned*)&h;
}

// ---------------- routing (validated round 2/7) ----------------
__global__ void router_kernel(const float* __restrict__ x,
                              const float* __restrict__ gw) {
    int n = blockIdx.x;
    int warp = threadIdx.x >> 5, lane = threadIdx.x & 31;
    const float4* xr = (const float4*)(x + (size_t)n * Dh);
    const float4* gr = (const float4*)(gw + (size_t)warp * Dh);
    float s = 0.f;
    for (int i = lane; i < Dh / 4; i += 32) {
        float4 a = xr[i], b = gr[i];
        s += a.x * b.x + a.y * b.y + a.z * b.z + a.w * b.w;
    }
    #pragma unroll
    for (int o = 16; o; o >>= 1) s += __shfl_xor_sync(0xffffffffu, s, o);
    if (lane == 0) g_logits[n * NE + warp] = s;
}

__global__ void colsum_kernel() {
    int warp = threadIdx.x >> 5, lane = threadIdx.x & 31;
    if (warp >= NE) return;
    float s = 0.f;
    for (int n = lane; n < NTOK; n += 32) s += g_logits[n * NE + warp];
    #pragma unroll
    for (int o = 16; o; o >>= 1) s += __shfl_xor_sync(0xffffffffu, s, o);
    if (lane == 0) g_sums[warp] = s;
}

__global__ void topk_kernel() {
    int s0 = 0; float b0 = g_sums[0];
    for (int e = 1; e < NE; e++) { float v = g_sums[e]; if (v > b0) { b0 = v; s0 = e; } }
    int s1 = -1; float b1 = -3.4e38f;
    for (int e = 0; e < NE; e++) {
        if (e == s0) continue;
        float v = g_sums[e]; if (v > b1) { b1 = v; s1 = e; }
    }
    g_sel[0] = s0; g_sel[1] = s1;
}

__global__ void weights_kernel() {
    int n = blockIdx.x * blockDim.x + threadIdx.x;
    if (n >= NTOK) return;
    float l0 = g_logits[n * NE + g_sel[0]];
    float l1 = g_logits[n * NE + g_sel[1]];
    float m = fmaxf(l0, l1);
    float e0 = expf(l0 - m), e1 = expf(l1 - m);
    float inv = 1.f / (e0 + e1);
    g_rw[n * 2 + 0] = e0 * inv;
    g_rw[n * 2 + 1] = e1 * inv;
}

// ---------------- fp16 MMA tiled GEMMs --------------------------------------
// Block tile 128x128, K-tile 32. 8 warps in 2x4 layout, warp tile 64x32.
// mma.sync.m16n8k16.f16 with fp32 accumulate (same 10-bit mantissa as tf32).
// smem: half tiles, row stride 40 halves (80B) -> conflict-free fragment LDS.
#define HSTR 40

#define MMA_F16(c, a, b)                                                      \
    asm volatile(                                                             \
        "mma.sync.aligned.m16n8k16.row.col.f32.f16.f16.f32 "                  \
        "{%0,%1,%2,%3}, {%4,%5,%6,%7}, {%8,%9}, {%0,%1,%2,%3};\n"             \
        : "+f"(c[0]), "+f"(c[1]), "+f"(c[2]), "+f"(c[3])                      \
        : "r"(a[0]), "r"(a[1]), "r"(a[2]), "r"(a[3]), "r"(b[0]), "r"(b[1]))

// LDG next tile into registers.
// A: round-7-validated mapping (4x LDG.128, rows tid>>3 + 32it, k = (tid&7)*4).
// B: k-strided LDG.32, lane-coalesced along n (tile transposed at STS).
__device__ __forceinline__ void ldg_tiles(float4 rA[4], float rBv[16],
                                          const float* Ag, int lda,
                                          const float* Bg, int ldb, int k0) {
    int tid = threadIdx.x;
    int ra = tid >> 3, ca = (tid & 7) * 4;
    #pragma unroll
    for (int it = 0; it < 4; it++)
        rA[it] = *(const float4*)(Ag + (size_t)(ra + it * 32) * lda + k0 + ca);

    int nb = tid & 127, kh = (tid >> 7) * 16;
    #pragma unroll
    for (int kk = 0; kk < 16; kk++)
        rBv[kk] = Bg[(size_t)(k0 + kh + kk) * ldb + nb];
}

// STS with fp32->fp16 conversion. B stored k-major (sB[n][k]); k-pair order
// rotated per lane to avoid the n = n+8 (mod) bank collision.
__device__ __forceinline__ void sts_tiles(__half* sA, __half* sB,
                                          const float4 rA[4], const float rBv[16]) {
    int tid = threadIdx.x;
    int ra = tid >> 3, ca = (tid & 7) * 4;
    #pragma unroll
    for (int it = 0; it < 4; it++) {
        uint2 p = { pack_h2(rA[it].x, rA[it].y), pack_h2(rA[it].z, rA[it].w) };
        *(uint2*)(sA + (ra + it * 32) * HSTR + ca) = p;
    }
    int nb = tid & 127, kh = (tid >> 7) * 16;
    int rot = (tid >> 2) & 7;
    #pragma unroll
    for (int m = 0; m < 8; m++) {
        int mm = (m + rot) & 7;
        *(unsigned*)(sB + nb * HSTR + kh + 2 * mm) =
            pack_h2(rBv[2 * mm], rBv[2 * mm + 1]);
    }
}

// mainloop: acc += A[128 x K] * B[K x 128] (reg-staged pipeline, round-7 form)
__device__ __forceinline__ void mma_mainloop(float acc[4][4][4],
                                             const float* Ag, int lda,
                                             const float* Bg, int ldb,
                                             int ktiles,
                                             __half* sA, __half* sB) {
    const int lane = threadIdx.x & 31;
    const int warp = threadIdx.x >> 5;
    const int grp = lane >> 2, tq = lane & 3;
    const int wm = warp >> 2, wn = warp & 3;

    float4 rA[4]; float rBv[16];
    ldg_tiles(rA, rBv, Ag, lda, Bg, ldb, 0);
    sts_tiles(sA, sB, rA, rBv);

    for (int kt = 0; kt < ktiles; kt++) {
        __syncthreads();                       // tile kt visible in smem
        if (kt + 1 < ktiles)                   // issue next LDGs early
            ldg_tiles(rA, rBv, Ag, lda, Bg, ldb, (kt + 1) * 32);

        #pragma unroll
        for (int kc = 0; kc < 2; kc++) {       // two k16 chunks per k-tile
            unsigned af[4][4];
            #pragma unroll
            for (int i = 0; i < 4; i++) {
                const __half* pa = sA + (wm * 64 + i * 16 + grp) * HSTR
                                      + kc * 16 + 2 * tq;
                af[i][0] = *(const unsigned*)pa;
                af[i][1] = *(const unsigned*)(pa + 8 * HSTR);
                af[i][2] = *(const unsigned*)(pa + 8);
                af[i][3] = *(const unsigned*)(pa + 8 * HSTR + 8);
            }
            unsigned bf[4][2];
            #pragma unroll
            for (int j = 0; j < 4; j++) {
                const __half* pb = sB + (wn * 32 + j * 8 + grp) * HSTR
                                      + kc * 16 + 2 * tq;
                bf[j][0] = *(const unsigned*)pb;
                bf[j][1] = *(const unsigned*)(pb + 8);
            }
            #pragma unroll
            for (int i = 0; i < 4; i++)
                #pragma unroll
                for (int j = 0; j < 4; j++) MMA_F16(acc[i][j], af[i], bf[j]);
        }

        __syncthreads();                       // all reads of tile kt done
        if (kt + 1 < ktiles)
            sts_tiles(sA, sB, rA, rBv);        // overwrite with tile kt+1
    }
}

// GEMM1: H = gelu(X @ W1[e] + b1[e])
__global__ __launch_bounds__(256, 2) void gemm1_kernel(
    const float* __restrict__ X, const float* __restrict__ W1all,
    const float* __restrict__ B1all, int slot) {
    __shared__ __half sA[128 * HSTR];
    __shared__ __half sB[128 * HSTR];

    const int e = g_sel[slot];
    const float* __restrict__ Bg = W1all + (size_t)e * Dh * FF + blockIdx.x * 128;
    const float* __restrict__ bias = B1all + (size_t)e * FF;
    const int m0 = blockIdx.y * 128, n0 = blockIdx.x * 128;
    const float* __restrict__ Ag = X + (size_t)m0 * Dh;

    float acc[4][4][4];
    #pragma unroll
    for (int i = 0; i < 4; i++)
        #pragma unroll
        for (int j = 0; j < 4; j++)
            #pragma unroll
            for (int r = 0; r < 4; r++) acc[i][j][r] = 0.f;

    mma_mainloop(acc, Ag, Dh, Bg, FF, Dh / 32, sA, sB);

    const int warp = threadIdx.x >> 5, lane = threadIdx.x & 31;
    const int grp = lane >> 2, tq = lane & 3;
    const int wm = warp >> 2, wn = warp & 3;
    #pragma unroll
    for (int i = 0; i < 4; i++) {
        int r0 = m0 + wm * 64 + i * 16 + grp;
        #pragma unroll
        for (int j = 0; j < 4; j++) {
            int cb = n0 + wn * 32 + j * 8 + tq * 2;
            float bi0 = bias[cb], bi1 = bias[cb + 1];
            float2 v0 = { gelu_tanh(acc[i][j][0] + bi0), gelu_tanh(acc[i][j][1] + bi1) };
            float2 v1 = { gelu_tanh(acc[i][j][2] + bi0), gelu_tanh(acc[i][j][3] + bi1) };
            *(float2*)&g_H[(size_t)r0 * FF + cb] = v0;
            *(float2*)&g_H[(size_t)(r0 + 8) * FF + cb] = v1;
        }
    }
}

// GEMM2: out (+)= rw[:,slot] * (H @ W2[e] + b2[e])
__global__ __launch_bounds__(256, 2) void gemm2_kernel(
    const float* __restrict__ W2all, const float* __restrict__ B2all,
    float* __restrict__ Out, int slot) {
    __shared__ __half sA[128 * HSTR];
    __shared__ __half sB[128 * HSTR];

    const int e = g_sel[slot];
    const float* __restrict__ Bg = W2all + (size_t)e * FF * Dh + blockIdx.x * 128;
    const float* __restrict__ bias = B2all + (size_t)e * Dh;
    const int m0 = blockIdx.y * 128, n0 = blockIdx.x * 128;
    const float* __restrict__ Ag = g_H + (size_t)m0 * FF;

    float acc[4][4][4];
    #pragma unroll
    for (int i = 0; i < 4; i++)
        #pragma unroll
        for (int j = 0; j < 4; j++)
            #pragma unroll
            for (int r = 0; r < 4; r++) acc[i][j][r] = 0.f;

    mma_mainloop(acc, Ag, FF, Bg, Dh, FF / 32, sA, sB);

    const int warp = threadIdx.x >> 5, lane = threadIdx.x & 31;
    const int grp = lane >> 2, tq = lane & 3;
    const int wm = warp >> 2, wn = warp & 3;
    #pragma unroll
    for (int i = 0; i < 4; i++) {
        int r0 = m0 + wm * 64 + i * 16 + grp;
        float wA = g_rw[r0 * 2 + slot];
        float wB = g_rw[(r0 + 8) * 2 + slot];
        #pragma unroll
        for (int j = 0; j < 4; j++) {
            int cb = n0 + wn * 32 + j * 8 + tq * 2;
            float bi0 = bias[cb], bi1 = bias[cb + 1];
            float o00 = wA * (acc[i][j][0] + bi0);
            float o01 = wA * (acc[i][j][1] + bi1);
            float o10 = wB * (acc[i][j][2] + bi0);
            float o11 = wB * (acc[i][j][3] + bi1);
            float2* p0 = (float2*)&Out[(size_t)r0 * Dh + cb];
            float2* p1 = (float2*)&Out[(size_t)(r0 + 8) * Dh + cb];
            if (slot == 0) {
                *p0 = make_float2(o00, o01);
                *p1 = make_float2(o10, o11);
            } else {
                float2 t0 = *p0; t0.x += o00; t0.y += o01; *p0 = t0;
                float2 t1 = *p1; t1.x += o10; t1.y += o11; *p1 = t1;
            }
        }
    }
}

// ---------------- launch ----------------
extern "C" void kernel_launch(void* const* d_in, const int* in_sizes, int n_in,
                              void* d_out, int out_size) {
    const float* x  = (const float*)d_in[0];   // [2,4096,2048]
    const float* gw = (const float*)d_in[1];   // [8,2048]
    const float* w1 = (const float*)d_in[2];   // [8,2048,8192]
    const float* b1 = (const float*)d_in[3];   // [8,8192]
    const float* w2 = (const float*)d_in[4];   // [8,8192,2048]
    const float* b2 = (const float*)d_in[5];   // [8,2048]
    float* out = (float*)d_out;                // [2,4096,2048]

    router_kernel<<<NTOK, 256>>>(x, gw);
    colsum_kernel<<<1, 256>>>();
    topk_kernel<<<1, 1>>>();
    weights_kernel<<<NTOK / 256, 256>>>();

    for (int slot = 0; slot < TOPK; ++slot) {
        gemm1_kernel<<<dim3(FF / 128, NTOK / 128), 256>>>(x, w1, b1, slot);
        gemm2_kernel<<<dim3(Dh / 128, NTOK / 128), 256>>>(w2, b2, out, slot);
    }
}